// round 2
// baseline (speedup 1.0000x reference)
#include <cuda_runtime.h>

// ---- problem constants ----
#define A_   3
#define H_   128
#define W_   128
#define C_   2
#define ATTRS 7
#define B_   64
#define T_   2
#define NCELLS (B_*A_*H_*W_)               // 3,145,728
#define CELLS_PER_CHUNK 1024
#define NCHUNKS (NCELLS/CELLS_PER_CHUNK)   // 3072
#define CHUNKS_PER_BATCH ((A_*H_*W_)/CELLS_PER_CHUNK)  // 48
#define THREADS 256
#define GRID    1024                        // 3 chunks per block (exact)
#define F4_PER_CHUNK (CELLS_PER_CHUNK*ATTRS/4)  // 1792 float4 = 28 KB

// ---- persistent device state (zero-init at module load; self-resetting) ----
__device__ double       g_acc[6] = {0, 0, 0, 0, 0, 0};
__device__ unsigned int g_done   = 0;

// Per-(b,t) target parameters, computed inline from tiny inputs.
struct Tgt {
    float cx, cy, bw, bh, ar, cl;
    int   key;
};

__device__ __forceinline__ Tgt make_tgt(const float* __restrict__ boxes,
                                        const int*   __restrict__ labels,
                                        const float* __restrict__ areas,
                                        int b, int t) {
    const float* bx = boxes + (size_t)(b * T_ + t) * 4;
    float x1 = __ldg(bx + 0), y1 = __ldg(bx + 1);
    float x2 = __ldg(bx + 2), y2 = __ldg(bx + 3);
    Tgt o;
    o.cx = (x1 + x2) * 0.5f;
    o.cy = (y1 + y2) * 0.5f;
    o.bw = x2 - x1;
    o.bh = y2 - y1;
    o.ar = (o.bw - o.cx) * (o.bh - o.cy);   // area_t in reference

    // best anchor: argmin |anchor_area - area| (first wins ties)
    float ar = __ldg(areas + b * T_ + t);
    float d0 = fabsf(10440.0f  - ar);       // 116*90
    float d1 = fabsf(30888.0f  - ar);       // 156*198
    float d2 = fabsf(121598.0f - ar);       // 373*326
    int   an = 0; float m = d0;
    if (d1 < m) { m = d1; an = 1; }
    if (d2 < m) { an = 2; }

    int cX = (int)((o.bw - o.cx) * 0.125f);  // stride 8 exactly
    int cY = (int)((o.bh - o.cy) * 0.125f);
    o.key = (an << 16) | (cX << 8) | cY;

    int lab = __ldg(labels + b * T_ + t);
    // matched[...,5]: t==0 -> one_hot(lab,2)[1]; t==1 -> one_hot(lab-1,2)[1]
    o.cl = (t == 0) ? ((lab == 1) ? 1.0f : 0.0f)
                    : ((lab == 2) ? 1.0f : 0.0f);
    return o;
}

// ============================================================
// Single fused kernel: stream 88 MB, accumulate 6 loss sums,
// last-finished block finalizes and writes the 7 outputs.
// ============================================================
__global__ __launch_bounds__(THREADS)
void yolo_fused(const float4* __restrict__ q,
                const float*  __restrict__ boxes,
                const int*    __restrict__ labels,
                const float*  __restrict__ areas,
                float* __restrict__ out) {
    __shared__ float4 s[F4_PER_CHUNK];        // 28 KB
    __shared__ float  red[6][THREADS / 32];

    const int tid = threadIdx.x;

    float sx = 0.f, sy = 0.f, sw = 0.f, sh = 0.f, sc = 0.f, sl = 0.f;

    for (int chunk = blockIdx.x; chunk < NCHUNKS; chunk += gridDim.x) {
        __syncthreads();   // protect smem reuse across iterations

        // -- coalesced global -> smem (7 x float4 per thread, MLP=7) --
        size_t base = (size_t)chunk * F4_PER_CHUNK;
        #pragma unroll
        for (int m = 0; m < 7; m++)
            s[tid + m * THREADS] = q[base + tid + m * THREADS];

        // -- per-batch target constants (uniform, L1-broadcast loads) --
        int b = chunk / CHUNKS_PER_BATCH;
        Tgt t0 = make_tgt(boxes, labels, areas, b, 0);
        Tgt t1 = make_tgt(boxes, labels, areas, b, 1);

        __syncthreads();

        // -- my 4 cells: 28 floats, conflict-free LDS.128 --
        float f[28];
        float4* fp = reinterpret_cast<float4*>(f);
        #pragma unroll
        for (int m = 0; m < 7; m++)
            fp[m] = s[tid * 7 + m];

        int n0 = chunk * CELLS_PER_CHUNK + tid * 4;
        #pragma unroll
        for (int k = 0; k < 4; k++) {
            int n = n0 + k;
            int j = n & (W_ - 1);
            int i = (n >> 7) & (H_ - 1);
            int a = (n >> 14) % A_;

            float xr   = f[7 * k + 0];
            float yr   = f[7 * k + 1];
            float w    = f[7 * k + 2];
            float h    = f[7 * k + 3];
            float conf = f[7 * k + 4];

            float fi = (float)i, fj = (float)j;
            float xp = xr - fi;
            float yp = yr - fj;
            float hw = 0.5f * w, hh = 0.5f * h;
            float px1 = xp - hw, px2 = xp + hw;
            float py1 = yp - hh, py2 = yp + hh;
            float area_p = (px2 - px1) * (py2 - py1);

            // suppress: max IoU over the 2 targets > 0.5 (division-free)
            float ix0 = fmaxf(fminf(px2, t0.bw) - fmaxf(px1, t0.cx), 0.0f);
            float iy0 = fmaxf(fminf(py2, t0.bh) - fmaxf(py1, t0.cy), 0.0f);
            float in0 = ix0 * iy0;
            bool sup  = in0 > 0.5f * (area_p + t0.ar - in0 + 1e-16f);

            float ix1 = fmaxf(fminf(px2, t1.bw) - fmaxf(px1, t1.cx), 0.0f);
            float iy1 = fmaxf(fminf(py2, t1.bh) - fmaxf(py1, t1.cy), 0.0f);
            float in1 = ix1 * iy1;
            sup = sup || (in1 > 0.5f * (area_p + t1.ar - in1 + 1e-16f));

            int key = (a << 16) | (i << 8) | j;
            if (key == t1.key || key == t0.key) {
                // exact cell: target t=1 wins on overwrite
                bool  is1 = (key == t1.key);
                float cx = is1 ? t1.cx : t0.cx;
                float cy = is1 ? t1.cy : t0.cy;
                float bw = is1 ? t1.bw : t0.bw;
                float bh = is1 ? t1.bh : t0.bh;
                float tc = is1 ? t1.cl : t0.cl;

                float dX = xp - (cx - fi);
                float dY = yp - (cy - fj);
                float dW = w - bw;
                float dH = h - bh;
                sx += dX * dX;  sy += dY * dY;
                sw += dW * dW;  sh += dH * dH;

                sc += -fmaxf(__logf(conf), -100.0f);

                float p0 = f[7 * k + 5];
                float p1 = f[7 * k + 6];
                if (tc != 0.0f) {
                    sl += -fmaxf(__logf(p0), -100.0f)
                        -  fmaxf(__logf(p1), -100.0f);
                } else {
                    sl += -fmaxf(__logf(1.0f - p0), -100.0f)
                        -  fmaxf(__logf(1.0f - p1), -100.0f);
                }
            } else if (!sup) {
                sc += -fmaxf(__logf(1.0f - conf), -100.0f);
            }
            // suppressed non-exact: conff=0, t=0 -> -log1p(0) = 0
        }
    }

    // -- reduction: warp shuffle -> block smem -> 6 double atomics --
    #pragma unroll
    for (int o = 16; o > 0; o >>= 1) {
        sx += __shfl_down_sync(0xffffffffu, sx, o);
        sy += __shfl_down_sync(0xffffffffu, sy, o);
        sw += __shfl_down_sync(0xffffffffu, sw, o);
        sh += __shfl_down_sync(0xffffffffu, sh, o);
        sc += __shfl_down_sync(0xffffffffu, sc, o);
        sl += __shfl_down_sync(0xffffffffu, sl, o);
    }
    int warp = tid >> 5, lane = tid & 31;
    if (lane == 0) {
        red[0][warp] = sx; red[1][warp] = sy; red[2][warp] = sw;
        red[3][warp] = sh; red[4][warp] = sc; red[5][warp] = sl;
    }
    __syncthreads();
    if (tid < 6) {
        float acc = 0.f;
        #pragma unroll
        for (int wv = 0; wv < THREADS / 32; wv++) acc += red[tid][wv];
        atomicAdd(&g_acc[tid], (double)acc);
    }
    __syncthreads();   // all 6 atomics of this block issued before the fence

    // -- last-block-done finalization (replaces the 3rd launch) --
    if (tid == 0) {
        __threadfence();
        unsigned int old = atomicAdd(&g_done, 1u);
        if (old == gridDim.x - 1) {
            __threadfence();   // acquire: all blocks' g_acc adds visible
            double N = (double)NCELLS;
            double xL = g_acc[0] / N;
            double yL = g_acc[1] / N;
            double wL = g_acc[2] / N;
            double hL = g_acc[3] / N;
            double confL = g_acc[4] / N;
            double clsL  = g_acc[5] / (2.0 * N);
            double loss = 2.5 * (xL + yL) + 2.5 * (wL + hL) + confL + clsL;
            out[0] = (float)loss;
            out[1] = (float)xL;
            out[2] = (float)yL;
            out[3] = (float)wL;
            out[4] = (float)hL;
            out[5] = (float)confL;
            out[6] = (float)clsL;
            // reset persistent state for the next graph replay
            #pragma unroll
            for (int i = 0; i < 6; i++) g_acc[i] = 0.0;
            g_done = 0;
        }
    }
}

extern "C" void kernel_launch(void* const* d_in, const int* in_sizes, int n_in,
                              void* d_out, int out_size) {
    const float* output = (const float*)d_in[0];
    const float* boxes  = (const float*)d_in[1];
    const int*   labels = (const int*)  d_in[2];
    const float* areas  = (const float*)d_in[3];

    yolo_fused<<<GRID, THREADS>>>((const float4*)output,
                                  boxes, labels, areas, (float*)d_out);
}

// round 3
// speedup vs baseline: 1.1082x; 1.1082x over previous
#include <cuda_runtime.h>

// ---- problem constants ----
#define A_   3
#define H_   128
#define W_   128
#define ATTRS 7
#define B_   64
#define T_   2
#define NCELLS (B_*A_*H_*W_)                  // 3,145,728
#define CELLS_PER_CHUNK 512
#define NCHUNKS (NCELLS/CELLS_PER_CHUNK)      // 6144
#define CHUNKS_PER_BATCH ((A_*H_*W_)/CELLS_PER_CHUNK)  // 96
#define THREADS 128
#define GRID    1024                          // 6144/1024 = 6 chunks/block exact
#define F4_PER_CHUNK (CELLS_PER_CHUNK*ATTRS/4)  // 896 float4 = 14 KB

// ---- persistent device state (zero-init at load; self-resetting) ----
__device__ double       g_acc[6] = {0, 0, 0, 0, 0, 0};
__device__ unsigned int g_done   = 0;

struct Tgt { float cx, cy, bw, bh, ar, cl; int key; };

__device__ __forceinline__ Tgt make_tgt(const float* __restrict__ boxes,
                                        const int*   __restrict__ labels,
                                        const float* __restrict__ areas,
                                        int b, int t) {
    const float* bx = boxes + (size_t)(b * T_ + t) * 4;
    float x1 = __ldg(bx + 0), y1 = __ldg(bx + 1);
    float x2 = __ldg(bx + 2), y2 = __ldg(bx + 3);
    Tgt o;
    o.cx = (x1 + x2) * 0.5f;
    o.cy = (y1 + y2) * 0.5f;
    o.bw = x2 - x1;
    o.bh = y2 - y1;
    o.ar = (o.bw - o.cx) * (o.bh - o.cy);    // area_t in reference

    float ar = __ldg(areas + b * T_ + t);
    float d0 = fabsf(10440.0f  - ar);        // 116*90
    float d1 = fabsf(30888.0f  - ar);        // 156*198
    float d2 = fabsf(121598.0f - ar);        // 373*326
    int   an = 0; float m = d0;
    if (d1 < m) { m = d1; an = 1; }
    if (d2 < m) { an = 2; }

    int cX = (int)((o.bw - o.cx) * 0.125f);  // /8 exact
    int cY = (int)((o.bh - o.cy) * 0.125f);
    o.key = (an << 16) | (cX << 8) | cY;

    int lab = __ldg(labels + b * T_ + t);
    o.cl = (t == 0) ? ((lab == 1) ? 1.0f : 0.0f)
                    : ((lab == 2) ? 1.0f : 0.0f);
    return o;
}

// ============================================================
// Single fused kernel, cp.async double-buffered pipeline.
// ============================================================
__global__ __launch_bounds__(THREADS, 8)
void yolo_fused(const float4* __restrict__ q,
                const float*  __restrict__ boxes,
                const int*    __restrict__ labels,
                const float*  __restrict__ areas,
                float* __restrict__ out) {
    __shared__ float4 s[2][F4_PER_CHUNK];     // 2 x 14 KB
    __shared__ float  red[6][THREADS / 32];

    const int tid = threadIdx.x;

    float sx = 0.f, sy = 0.f, sw = 0.f, sh = 0.f, sc = 0.f, sl = 0.f;

    // prologue: async-load first chunk into buffer 0
    {
        unsigned dst = (unsigned)__cvta_generic_to_shared(&s[0][tid]);
        const float4* src = q + (size_t)blockIdx.x * F4_PER_CHUNK + tid;
        #pragma unroll
        for (int m = 0; m < 7; m++)
            asm volatile("cp.async.cg.shared.global [%0], [%1], 16;"
                         :: "r"(dst + m * THREADS * 16), "l"(src + m * THREADS));
        asm volatile("cp.async.commit_group;");
    }

    int buf = 0;
    for (int chunk = blockIdx.x; chunk < NCHUNKS; chunk += GRID) {
        // issue loads for the NEXT chunk into the other buffer
        int next = chunk + GRID;
        if (next < NCHUNKS) {
            unsigned dst = (unsigned)__cvta_generic_to_shared(&s[buf ^ 1][tid]);
            const float4* src = q + (size_t)next * F4_PER_CHUNK + tid;
            #pragma unroll
            for (int m = 0; m < 7; m++)
                asm volatile("cp.async.cg.shared.global [%0], [%1], 16;"
                             :: "r"(dst + m * THREADS * 16), "l"(src + m * THREADS));
        }
        asm volatile("cp.async.commit_group;");
        asm volatile("cp.async.wait_group 1;" ::: "memory");  // chunk's data done
        __syncthreads();

        // per-batch target constants (uniform broadcast loads)
        int b = chunk / CHUNKS_PER_BATCH;
        Tgt t0 = make_tgt(boxes, labels, areas, b, 0);
        Tgt t1 = make_tgt(boxes, labels, areas, b, 1);

        // my 4 cells: 28 floats via 7 LDS.128
        float f[28];
        float4* fp = reinterpret_cast<float4*>(f);
        #pragma unroll
        for (int m = 0; m < 7; m++)
            fp[m] = s[buf][tid * 7 + m];

        int n0 = chunk * CELLS_PER_CHUNK + tid * 4;
        #pragma unroll
        for (int k = 0; k < 4; k++) {
            int n = n0 + k;
            int j = n & (W_ - 1);
            int i = (n >> 7) & (H_ - 1);
            int a = (n >> 14) % A_;

            float xr   = f[7 * k + 0];
            float yr   = f[7 * k + 1];
            float w    = f[7 * k + 2];
            float h    = f[7 * k + 3];
            float conf = f[7 * k + 4];

            float fi = (float)i, fj = (float)j;
            float xp = xr - fi;
            float yp = yr - fj;
            float hw = 0.5f * w, hh = 0.5f * h;
            float px1 = xp - hw, px2 = xp + hw;
            float py1 = yp - hh, py2 = yp + hh;
            float area_p = (px2 - px1) * (py2 - py1);

            // suppress: max IoU over the 2 targets > 0.5 (division-free)
            float ix0 = fmaxf(fminf(px2, t0.bw) - fmaxf(px1, t0.cx), 0.0f);
            float iy0 = fmaxf(fminf(py2, t0.bh) - fmaxf(py1, t0.cy), 0.0f);
            float in0 = ix0 * iy0;
            bool sup  = in0 > 0.5f * (area_p + t0.ar - in0 + 1e-16f);

            float ix1 = fmaxf(fminf(px2, t1.bw) - fmaxf(px1, t1.cx), 0.0f);
            float iy1 = fmaxf(fminf(py2, t1.bh) - fmaxf(py1, t1.cy), 0.0f);
            float in1 = ix1 * iy1;
            sup = sup || (in1 > 0.5f * (area_p + t1.ar - in1 + 1e-16f));

            int key = (a << 16) | (i << 8) | j;
            if (key == t1.key || key == t0.key) {
                bool  is1 = (key == t1.key);     // target 1 wins on overwrite
                float cx = is1 ? t1.cx : t0.cx;
                float cy = is1 ? t1.cy : t0.cy;
                float bw = is1 ? t1.bw : t0.bw;
                float bh = is1 ? t1.bh : t0.bh;
                float tc = is1 ? t1.cl : t0.cl;

                float dX = xp - (cx - fi);
                float dY = yp - (cy - fj);
                float dW = w - bw;
                float dH = h - bh;
                sx += dX * dX;  sy += dY * dY;
                sw += dW * dW;  sh += dH * dH;

                sc += -fmaxf(__logf(conf), -100.0f);

                float p0 = f[7 * k + 5];
                float p1 = f[7 * k + 6];
                if (tc != 0.0f) {
                    sl += -fmaxf(__logf(p0), -100.0f)
                        -  fmaxf(__logf(p1), -100.0f);
                } else {
                    sl += -fmaxf(__logf(1.0f - p0), -100.0f)
                        -  fmaxf(__logf(1.0f - p1), -100.0f);
                }
            } else if (!sup) {
                sc += -fmaxf(__logf(1.0f - conf), -100.0f);
            }
        }

        __syncthreads();   // done reading s[buf] before it is refilled
        buf ^= 1;
    }

    // -- reduction: warp shuffle -> block smem -> 6 double atomics --
    #pragma unroll
    for (int o = 16; o > 0; o >>= 1) {
        sx += __shfl_down_sync(0xffffffffu, sx, o);
        sy += __shfl_down_sync(0xffffffffu, sy, o);
        sw += __shfl_down_sync(0xffffffffu, sw, o);
        sh += __shfl_down_sync(0xffffffffu, sh, o);
        sc += __shfl_down_sync(0xffffffffu, sc, o);
        sl += __shfl_down_sync(0xffffffffu, sl, o);
    }
    int warp = tid >> 5, lane = tid & 31;
    if (lane == 0) {
        red[0][warp] = sx; red[1][warp] = sy; red[2][warp] = sw;
        red[3][warp] = sh; red[4][warp] = sc; red[5][warp] = sl;
    }
    __syncthreads();
    if (tid < 6) {
        float acc = 0.f;
        #pragma unroll
        for (int wv = 0; wv < THREADS / 32; wv++) acc += red[tid][wv];
        atomicAdd(&g_acc[tid], (double)acc);
    }
    __syncthreads();

    // -- last-block-done finalization --
    if (tid == 0) {
        __threadfence();
        unsigned int old = atomicAdd(&g_done, 1u);
        if (old == gridDim.x - 1) {
            __threadfence();
            double N = (double)NCELLS;
            double xL = g_acc[0] / N;
            double yL = g_acc[1] / N;
            double wL = g_acc[2] / N;
            double hL = g_acc[3] / N;
            double confL = g_acc[4] / N;
            double clsL  = g_acc[5] / (2.0 * N);
            double loss = 2.5 * (xL + yL) + 2.5 * (wL + hL) + confL + clsL;
            out[0] = (float)loss;
            out[1] = (float)xL;
            out[2] = (float)yL;
            out[3] = (float)wL;
            out[4] = (float)hL;
            out[5] = (float)confL;
            out[6] = (float)clsL;
            #pragma unroll
            for (int i = 0; i < 6; i++) g_acc[i] = 0.0;
            g_done = 0;
        }
    }
}

extern "C" void kernel_launch(void* const* d_in, const int* in_sizes, int n_in,
                              void* d_out, int out_size) {
    const float* output = (const float*)d_in[0];
    const float* boxes  = (const float*)d_in[1];
    const int*   labels = (const int*)  d_in[2];
    const float* areas  = (const float*)d_in[3];

    yolo_fused<<<GRID, THREADS>>>((const float4*)output,
                                  boxes, labels, areas, (float*)d_out);
}

// round 4
// speedup vs baseline: 1.2280x; 1.1081x over previous
#include <cuda_runtime.h>

// ---- problem constants ----
#define A_   3
#define H_   128
#define W_   128
#define ATTRS 7
#define B_   64
#define T_   2
#define NCELLS (B_*A_*H_*W_)                  // 3,145,728
#define CELLS_PER_CHUNK 512
#define NCHUNKS (NCELLS/CELLS_PER_CHUNK)      // 6144
#define CHUNKS_PER_BATCH ((A_*H_*W_)/CELLS_PER_CHUNK)  // 96
#define THREADS 128
#define GRID    1024                          // 6144/1024 = 6 chunks/block exact
#define F4_PER_CHUNK (CELLS_PER_CHUNK*ATTRS/4)  // 896 float4 = 14 KB

// ---- persistent device state (zero-init at load; self-resetting) ----
__device__ double       g_acc[6] = {0, 0, 0, 0, 0, 0};
__device__ unsigned int g_done   = 0;

struct Tgt { float cx, cy, bw, bh, ar, cl; int key; };

__device__ __forceinline__ Tgt make_tgt(const float* __restrict__ boxes,
                                        const int*   __restrict__ labels,
                                        const float* __restrict__ areas,
                                        int b, int t) {
    const float* bx = boxes + (size_t)(b * T_ + t) * 4;
    float x1 = __ldg(bx + 0), y1 = __ldg(bx + 1);
    float x2 = __ldg(bx + 2), y2 = __ldg(bx + 3);
    Tgt o;
    o.cx = (x1 + x2) * 0.5f;
    o.cy = (y1 + y2) * 0.5f;
    o.bw = x2 - x1;
    o.bh = y2 - y1;
    o.ar = (o.bw - o.cx) * (o.bh - o.cy);    // area_t in reference

    float ar = __ldg(areas + b * T_ + t);
    float d0 = fabsf(10440.0f  - ar);        // 116*90
    float d1 = fabsf(30888.0f  - ar);        // 156*198
    float d2 = fabsf(121598.0f - ar);        // 373*326
    int   an = 0; float m = d0;
    if (d1 < m) { m = d1; an = 1; }
    if (d2 < m) { an = 2; }

    int cX = (int)((o.bw - o.cx) * 0.125f);  // /8 exact
    int cY = (int)((o.bh - o.cy) * 0.125f);
    o.key = (an << 16) | (cX << 8) | cY;

    int lab = __ldg(labels + b * T_ + t);
    o.cl = (t == 0) ? ((lab == 1) ? 1.0f : 0.0f)
                    : ((lab == 2) ? 1.0f : 0.0f);
    return o;
}

// ============================================================
// Single fused kernel, cp.async double-buffered pipeline,
// one __logf per 4 cells (log of product of (1-conf)).
// ============================================================
__global__ __launch_bounds__(THREADS, 8)
void yolo_fused(const float4* __restrict__ q,
                const float*  __restrict__ boxes,
                const int*    __restrict__ labels,
                const float*  __restrict__ areas,
                float* __restrict__ out) {
    __shared__ float4 s[2][F4_PER_CHUNK];     // 2 x 14 KB
    __shared__ float  red[6][THREADS / 32];

    const int tid = threadIdx.x;

    float sx = 0.f, sy = 0.f, sw = 0.f, sh = 0.f, sc = 0.f, sl = 0.f;

    // prologue: async-load first chunk into buffer 0
    {
        unsigned dst = (unsigned)__cvta_generic_to_shared(&s[0][tid]);
        const float4* src = q + (size_t)blockIdx.x * F4_PER_CHUNK + tid;
        #pragma unroll
        for (int m = 0; m < 7; m++)
            asm volatile("cp.async.cg.shared.global [%0], [%1], 16;"
                         :: "r"(dst + m * THREADS * 16), "l"(src + m * THREADS));
        asm volatile("cp.async.commit_group;");
    }

    int buf = 0;
    for (int chunk = blockIdx.x; chunk < NCHUNKS; chunk += GRID) {
        // issue loads for the NEXT chunk into the other buffer
        int next = chunk + GRID;
        if (next < NCHUNKS) {
            unsigned dst = (unsigned)__cvta_generic_to_shared(&s[buf ^ 1][tid]);
            const float4* src = q + (size_t)next * F4_PER_CHUNK + tid;
            #pragma unroll
            for (int m = 0; m < 7; m++)
                asm volatile("cp.async.cg.shared.global [%0], [%1], 16;"
                             :: "r"(dst + m * THREADS * 16), "l"(src + m * THREADS));
        }
        asm volatile("cp.async.commit_group;");
        asm volatile("cp.async.wait_group 1;" ::: "memory");  // this chunk done
        __syncthreads();

        // per-batch target constants (uniform broadcast loads)
        int b = chunk / CHUNKS_PER_BATCH;
        Tgt t0 = make_tgt(boxes, labels, areas, b, 0);
        Tgt t1 = make_tgt(boxes, labels, areas, b, 1);

        // my 4 cells: 28 floats via 7 conflict-free LDS.128
        float f[28];
        float4* fp = reinterpret_cast<float4*>(f);
        #pragma unroll
        for (int m = 0; m < 7; m++)
            fp[m] = s[buf][tid * 7 + m];

        int n0 = chunk * CELLS_PER_CHUNK + tid * 4;
        float prod = 1.0f;   // product of (1-conf) over this thread's 4 cells
        #pragma unroll
        for (int k = 0; k < 4; k++) {
            int n = n0 + k;
            int j = n & (W_ - 1);
            int i = (n >> 7) & (H_ - 1);
            int a = (n >> 14) % A_;

            float xr   = f[7 * k + 0];
            float yr   = f[7 * k + 1];
            float w    = f[7 * k + 2];
            float h    = f[7 * k + 3];
            float conf = f[7 * k + 4];

            float fi = (float)i, fj = (float)j;
            float xp = xr - fi;
            float yp = yr - fj;
            float hw = 0.5f * w, hh = 0.5f * h;
            float px1 = xp - hw, px2 = xp + hw;
            float py1 = yp - hh, py2 = yp + hh;
            float area_p = (px2 - px1) * (py2 - py1);

            // suppress: max IoU over the 2 targets > 0.5 (division-free)
            float ix0 = fmaxf(fminf(px2, t0.bw) - fmaxf(px1, t0.cx), 0.0f);
            float iy0 = fmaxf(fminf(py2, t0.bh) - fmaxf(py1, t0.cy), 0.0f);
            float in0 = ix0 * iy0;
            bool sup  = in0 > 0.5f * (area_p + t0.ar - in0 + 1e-16f);

            float ix1 = fmaxf(fminf(px2, t1.bw) - fmaxf(px1, t1.cx), 0.0f);
            float iy1 = fmaxf(fminf(py2, t1.bh) - fmaxf(py1, t1.cy), 0.0f);
            float in1 = ix1 * iy1;
            sup = sup || (in1 > 0.5f * (area_p + t1.ar - in1 + 1e-16f));

            int key = (a << 16) | (i << 8) | j;
            bool exact = (key == t1.key) || (key == t0.key);
            if (exact) {
                // rare path: <=128 cells chip-wide. target 1 wins on overwrite
                bool  is1 = (key == t1.key);
                float cx = is1 ? t1.cx : t0.cx;
                float cy = is1 ? t1.cy : t0.cy;
                float bw = is1 ? t1.bw : t0.bw;
                float bh = is1 ? t1.bh : t0.bh;
                float tc = is1 ? t1.cl : t0.cl;

                float dX = xp - (cx - fi);
                float dY = yp - (cy - fj);
                float dW = w - bw;
                float dH = h - bh;
                sx += dX * dX;  sy += dY * dY;
                sw += dW * dW;  sh += dH * dH;

                sc += -fmaxf(__logf(conf), -100.0f);

                float p0 = f[7 * k + 5];
                float p1 = f[7 * k + 6];
                if (tc != 0.0f) {
                    sl += -fmaxf(__logf(p0), -100.0f)
                        -  fmaxf(__logf(p1), -100.0f);
                } else {
                    sl += -fmaxf(__logf(1.0f - p0), -100.0f)
                        -  fmaxf(__logf(1.0f - p1), -100.0f);
                }
            } else {
                // dense path: -log(1-conf) if not suppressed, else 0.
                // (1-conf) >= 2^-24 since conf in [0,1) fp32; reference's
                // -100 clamp can never fire on this branch.
                prod *= sup ? 1.0f : (1.0f - conf);
            }
        }
        // one MUFU per 4 cells; prod >= 2^-96 -> always normal
        sc -= __logf(prod);

        __syncthreads();   // done reading s[buf] before refill
        buf ^= 1;
    }

    // -- reduction: warp shuffle -> block smem -> 6 double atomics --
    #pragma unroll
    for (int o = 16; o > 0; o >>= 1) {
        sx += __shfl_down_sync(0xffffffffu, sx, o);
        sy += __shfl_down_sync(0xffffffffu, sy, o);
        sw += __shfl_down_sync(0xffffffffu, sw, o);
        sh += __shfl_down_sync(0xffffffffu, sh, o);
        sc += __shfl_down_sync(0xffffffffu, sc, o);
        sl += __shfl_down_sync(0xffffffffu, sl, o);
    }
    int warp = tid >> 5, lane = tid & 31;
    if (lane == 0) {
        red[0][warp] = sx; red[1][warp] = sy; red[2][warp] = sw;
        red[3][warp] = sh; red[4][warp] = sc; red[5][warp] = sl;
    }
    __syncthreads();
    if (tid < 6) {
        float acc = 0.f;
        #pragma unroll
        for (int wv = 0; wv < THREADS / 32; wv++) acc += red[tid][wv];
        atomicAdd(&g_acc[tid], (double)acc);
    }
    __syncthreads();

    // -- last-block-done finalization --
    if (tid == 0) {
        __threadfence();
        unsigned int old = atomicAdd(&g_done, 1u);
        if (old == gridDim.x - 1) {
            __threadfence();
            double N = (double)NCELLS;
            double xL = g_acc[0] / N;
            double yL = g_acc[1] / N;
            double wL = g_acc[2] / N;
            double hL = g_acc[3] / N;
            double confL = g_acc[4] / N;
            double clsL  = g_acc[5] / (2.0 * N);
            double loss = 2.5 * (xL + yL) + 2.5 * (wL + hL) + confL + clsL;
            out[0] = (float)loss;
            out[1] = (float)xL;
            out[2] = (float)yL;
            out[3] = (float)wL;
            out[4] = (float)hL;
            out[5] = (float)confL;
            out[6] = (float)clsL;
            #pragma unroll
            for (int i = 0; i < 6; i++) g_acc[i] = 0.0;
            g_done = 0;
        }
    }
}

extern "C" void kernel_launch(void* const* d_in, const int* in_sizes, int n_in,
                              void* d_out, int out_size) {
    const float* output = (const float*)d_in[0];
    const float* boxes  = (const float*)d_in[1];
    const int*   labels = (const int*)  d_in[2];
    const float* areas  = (const float*)d_in[3];

    yolo_fused<<<GRID, THREADS>>>((const float4*)output,
                                  boxes, labels, areas, (float*)d_out);
}